// round 15
// baseline (speedup 1.0000x reference)
#include <cuda_runtime.h>
#include <cuda_fp16.h>
#include <math.h>
#include <stdint.h>

// Problem constants
#define Bv 2
#define Sv 2048
#define Dv 1024
#define Hv 16
#define HDv 64
#define Mv (Bv*Sv)   // 4096 rows

// ---------------------------------------------------------------------------
// Scratch (device globals: no allocation allowed)
// ---------------------------------------------------------------------------
__device__ __align__(16) __half g_xh[(size_t)Mv * Dv];
__device__ __align__(16) __half g_wq[(size_t)3 * Dv * Dv];
__device__ __align__(16) __half g_qkvh[(size_t)Mv * 3 * Dv];
__device__ __align__(16) __half g_oh[(size_t)Mv * Dv];
__device__ __align__(16) __half g_wo[(size_t)Dv * Dv];

// ---------------------------------------------------------------------------
// PTX helpers
// ---------------------------------------------------------------------------
__device__ __forceinline__ uint32_t smem_u32(const void* p) {
    uint32_t a;
    asm("{ .reg .u64 t; cvta.to.shared.u64 t, %1; cvt.u32.u64 %0, t; }" : "=r"(a) : "l"(p));
    return a;
}
#define CP_ASYNC16(sm, g) \
    asm volatile("cp.async.cg.shared.global [%0], [%1], 16;" :: "r"(sm), "l"(g) : "memory")
#define CP_COMMIT() asm volatile("cp.async.commit_group;" ::: "memory")
#define CP_WAIT(n)  asm volatile("cp.async.wait_group %0;" :: "n"(n) : "memory")

#define LDSM_X4(r0, r1, r2, r3, addr) \
    asm volatile("ldmatrix.sync.aligned.m8n8.x4.shared.b16 {%0,%1,%2,%3}, [%4];" \
        : "=r"(r0), "=r"(r1), "=r"(r2), "=r"(r3) : "r"(addr))
#define LDSM_X4_T(r0, r1, r2, r3, addr) \
    asm volatile("ldmatrix.sync.aligned.m8n8.x4.trans.shared.b16 {%0,%1,%2,%3}, [%4];" \
        : "=r"(r0), "=r"(r1), "=r"(r2), "=r"(r3) : "r"(addr))

// fp16 mma, fp32 accumulate
#define MMAH(d, a, b) \
    asm volatile("mma.sync.aligned.m16n8k16.row.col.f32.f16.f16.f32 " \
        "{%0,%1,%2,%3}, {%4,%5,%6,%7}, {%8,%9}, {%0,%1,%2,%3};" \
        : "+f"((d)[0]), "+f"((d)[1]), "+f"((d)[2]), "+f"((d)[3]) \
        : "r"((a)[0]), "r"((a)[1]), "r"((a)[2]), "r"((a)[3]), "r"((b)[0]), "r"((b)[1]))

// pack(lo, hi) -> f16x2 register (lo in low 16 bits)
__device__ __forceinline__ uint32_t packh(float lo, float hi) {
    __half2 h = __floats2half2_rn(lo, hi);
    return *reinterpret_cast<uint32_t*>(&h);
}

// ---------------------------------------------------------------------------
// fp32 -> fp16 (single)
// ---------------------------------------------------------------------------
__global__ __launch_bounds__(256) void cvt_h(
    const float* __restrict__ in, __half* __restrict__ out, int n4)
{
    int i = blockIdx.x * blockDim.x + threadIdx.x;
    if (i >= n4) return;
    float4 v = ((const float4*)in)[i];
    ((uint2*)out)[i] = make_uint2(packh(v.x, v.y), packh(v.z, v.w));
}

// ---------------------------------------------------------------------------
// Persistent single-pass fp16 GEMM:  C[M,N] = A[M,K] * B[N,K]^T
// 128x128x32 CTA tile, 256 threads = 8 warps (64x32 each).
// 3-stage cp.async pipeline, 2 CTAs/SM (16 warps/SM for latency hiding).
// WB=1: write fp16; WB=0: write fp32.
// ---------------------------------------------------------------------------
#define BM 128
#define BN 128
#define BKc 32
#define TILE_BYT (128 * 80)           // 80B row stride
#define STAGE_BYT (2 * TILE_BYT)      // A, B
#define GEMM_SMEM (3 * STAGE_BYT)     // 61440 B
#define GEMM_GRID 296

__device__ __forceinline__ void load_stage(
    uint32_t sb, int s,
    const __half* __restrict__ A, const __half* __restrict__ B,
    int bm, int bn, int k0, int K, int tid)
{
    uint32_t base = sb + s * STAGE_BYT;
    #pragma unroll
    for (int j = 0; j < 2; ++j) {
        int idx = tid + j * 256;            // 0..511
        int row = idx >> 2, ch = idx & 3;
        CP_ASYNC16(base + row * 80 + ch * 16,
                   A + (size_t)(bm + row) * K + k0 + ch * 8);
        CP_ASYNC16(base + TILE_BYT + row * 80 + ch * 16,
                   B + (size_t)(bn + row) * K + k0 + ch * 8);
    }
}

template<int WB>
__global__ __launch_bounds__(256, 2) void gemm_mma_h(
    const __half* __restrict__ A, const __half* __restrict__ B,
    float* __restrict__ C, __half* __restrict__ Ch, int M, int K, int N)
{
    extern __shared__ char smem[];
    const uint32_t sb = smem_u32(smem);
    const int tid = threadIdx.x, wid = tid >> 5, lane = tid & 31;
    const int wm = (wid >> 2) * 64;       // 0 or 64
    const int wn = (wid & 3) * 32;        // 0, 32, 64, 96
    const uint32_t lrow = (lane & 15);
    const uint32_t lcol = (lane >> 4) * 16;
    const int ntn = N / BN;
    const int ntot = (M / BM) * ntn;
    const int NKB = K / BKc;              // 32

    for (int tix = blockIdx.x; tix < ntot; tix += (int)gridDim.x) {
        const int bm = (tix / ntn) * BM, bn = (tix % ntn) * BN;

        float acc[4][4][4];
        #pragma unroll
        for (int i = 0; i < 4; ++i)
            #pragma unroll
            for (int j = 0; j < 4; ++j)
                #pragma unroll
                for (int q = 0; q < 4; ++q) acc[i][j][q] = 0.f;

        load_stage(sb, 0, A, B, bm, bn, 0, K, tid);
        CP_COMMIT();
        load_stage(sb, 1, A, B, bm, bn, BKc, K, tid);
        CP_COMMIT();

        for (int kb = 0; kb < NKB; ++kb) {
            const int s = kb % 3;
            if (kb + 2 < NKB) {
                load_stage(sb, (kb + 2) % 3, A, B, bm, bn, (kb + 2) * BKc, K, tid);
                CP_COMMIT();
                CP_WAIT(2);
            } else if (kb + 1 < NKB) {
                CP_WAIT(1);
            } else {
                CP_WAIT(0);
            }
            __syncthreads();

            const uint32_t stb = sb + s * STAGE_BYT;
            #pragma unroll
            for (int ks = 0; ks < 2; ++ks) {
                const uint32_t koff = ks * 32 + lcol;
                uint32_t aa[4][4], bb[2][4];
                #pragma unroll
                for (int rt = 0; rt < 4; ++rt) {
                    uint32_t ro = (wm + rt * 16 + lrow) * 80 + koff;
                    LDSM_X4(aa[rt][0], aa[rt][1], aa[rt][2], aa[rt][3], stb + ro);
                }
                #pragma unroll
                for (int g = 0; g < 2; ++g) {
                    uint32_t ro = (wn + g * 16 + lrow) * 80 + koff;
                    LDSM_X4(bb[g][0], bb[g][1], bb[g][2], bb[g][3], stb + TILE_BYT + ro);
                }
                #pragma unroll
                for (int rt = 0; rt < 4; ++rt)
                    #pragma unroll
                    for (int g = 0; g < 2; ++g)
                        #pragma unroll
                        for (int sub = 0; sub < 2; ++sub) {
                            uint32_t bf[2] = { bb[g][sub], bb[g][sub + 2] };
                            MMAH(acc[rt][g * 2 + sub], aa[rt], bf);
                        }
            }
            __syncthreads();
        }

        const int r0 = bm + wm + (lane >> 2);
        const int c0 = bn + wn + (lane & 3) * 2;
        #pragma unroll
        for (int rt = 0; rt < 4; ++rt)
            #pragma unroll
            for (int ct = 0; ct < 4; ++ct) {
                size_t i0 = (size_t)(r0 + rt * 16) * N + c0 + ct * 8;
                size_t i1 = i0 + (size_t)8 * N;
                if (WB) {
                    *(uint32_t*)&Ch[i0] = packh(acc[rt][ct][0], acc[rt][ct][1]);
                    *(uint32_t*)&Ch[i1] = packh(acc[rt][ct][2], acc[rt][ct][3]);
                } else {
                    *(float2*)&C[i0] = make_float2(acc[rt][ct][0], acc[rt][ct][1]);
                    *(float2*)&C[i1] = make_float2(acc[rt][ct][2], acc[rt][ct][3]);
                }
            }
    }
}

// ---------------------------------------------------------------------------
// Flash attention, all single-pass fp16. CTA: 128 q-rows x 128 kv tile.
//   S = Qh*Kh ; O = Ph*Vh
// ---------------------------------------------------------------------------
#define BQa 128
#define BKVa 128
#define TST 144
#define SQH 0
#define KVB (128 * TST)
#define KVSTG (2 * 128 * TST)           // Kh + Vh
#define ATTN_SMEM (KVB + 2 * KVSTG)     // 92160 B

__global__ __launch_bounds__(256) void attn_mma(
    const __half* __restrict__ qkvh, __half* __restrict__ oh)
{
    extern __shared__ char smem[];
    const uint32_t sb = smem_u32(smem);
    const int tid = threadIdx.x, wid = tid >> 5, lane = tid & 31;
    const int qi = (int)gridDim.x - 1 - (int)blockIdx.x;   // heavy tiles first
    const int h = blockIdx.y, b = blockIdx.z;
    const int qbase = qi * BQa;
    const int wq = wid * 16;
    const uint32_t lrow = lane & 15, lcol = (lane >> 4) * 16;
    const size_t ld = 3 * Dv;

    // Load Q tile
    {
        const size_t base = ((size_t)b * Sv + qbase) * ld + (size_t)h * HDv;
        #pragma unroll
        for (int i = 0; i < 4; ++i) {
            int idx = tid + i * 256;            // 128 rows * 8 chunks
            int rr = (idx >> 3) & 127, ch = idx & 7;
            CP_ASYNC16(sb + SQH + rr * TST + ch * 16,
                       qkvh + base + (size_t)rr * ld + ch * 8);
        }
    }

    const int ntiles = qi + 1;
    // prologue: KV tile 0 -> stage 0 (Kh, Vh)
    {
        const size_t kbase = ((size_t)b * Sv) * ld + Dv + (size_t)h * HDv;
        #pragma unroll
        for (int i = 0; i < 8; ++i) {
            int idx = tid + i * 256;
            int t = idx >> 10, rr = (idx >> 3) & 127, ch = idx & 7;
            const __half* src = qkvh + kbase + (t ? Dv : 0) + (size_t)rr * ld + ch * 8;
            CP_ASYNC16(sb + KVB + t * (128 * TST) + rr * TST + ch * 16, src);
        }
    }
    CP_COMMIT();

    float s[16][4], o[8][4];
    #pragma unroll
    for (int t = 0; t < 8; ++t)
        #pragma unroll
        for (int e = 0; e < 4; ++e) o[t][e] = 0.f;
    float m0 = -1e30f, m1 = -1e30f, l0 = 0.f, l1 = 0.f;

    for (int j = 0; j < ntiles; ++j) {
        const int stg = j & 1;
        if (j + 1 < ntiles) {
            const size_t kbase = ((size_t)b * Sv + (size_t)(j + 1) * BKVa) * ld + Dv + (size_t)h * HDv;
            uint32_t s0 = sb + KVB + (stg ^ 1) * KVSTG;
            #pragma unroll
            for (int i = 0; i < 8; ++i) {
                int idx = tid + i * 256;
                int t = idx >> 10, rr = (idx >> 3) & 127, ch = idx & 7;
                const __half* src = qkvh + kbase + (t ? Dv : 0) + (size_t)rr * ld + ch * 8;
                CP_ASYNC16(s0 + t * (128 * TST) + rr * TST + ch * 16, src);
            }
            CP_COMMIT();
            CP_WAIT(1);
        } else {
            CP_WAIT(0);
        }
        __syncthreads();

        const uint32_t kh_b = sb + KVB + stg * KVSTG;
        const uint32_t vh_b = kh_b + 128 * TST;

        // S = Q K^T (single pass), 16 n8-tiles
        #pragma unroll
        for (int t = 0; t < 16; ++t)
            #pragma unroll
            for (int e = 0; e < 4; ++e) s[t][e] = 0.f;
        #pragma unroll
        for (int dc = 0; dc < 4; ++dc) {
            uint32_t qoff = (wq + lrow) * TST + dc * 32 + lcol;
            uint32_t qh[4];
            LDSM_X4(qh[0], qh[1], qh[2], qh[3], sb + SQH + qoff);
            #pragma unroll
            for (int ng = 0; ng < 8; ++ng) {
                uint32_t koff = (ng * 16 + lrow) * TST + dc * 32 + lcol;
                uint32_t kh[4];
                LDSM_X4(kh[0], kh[1], kh[2], kh[3], kh_b + koff);
                uint32_t b0h[2] = { kh[0], kh[2] }, b1h[2] = { kh[1], kh[3] };
                MMAH(s[2 * ng],     qh, b0h);
                MMAH(s[2 * ng + 1], qh, b1h);
            }
        }

        // scale + causal mask (diagonal tile only)
        const int row0 = qbase + wq + (lane >> 2);
        if (j == ntiles - 1) {
            #pragma unroll
            for (int t = 0; t < 16; ++t) {
                int colb = j * BKVa + 8 * t + (lane & 3) * 2;
                #pragma unroll
                for (int e = 0; e < 4; ++e) {
                    int col = colb + (e & 1);
                    int row = (e < 2) ? row0 : row0 + 8;
                    s[t][e] = (col > row) ? -1e30f : s[t][e] * 0.125f;
                }
            }
        } else {
            #pragma unroll
            for (int t = 0; t < 16; ++t)
                #pragma unroll
                for (int e = 0; e < 4; ++e) s[t][e] *= 0.125f;
        }

        // online softmax
        float mx0 = -1e30f, mx1 = -1e30f;
        #pragma unroll
        for (int t = 0; t < 16; ++t) {
            mx0 = fmaxf(mx0, fmaxf(s[t][0], s[t][1]));
            mx1 = fmaxf(mx1, fmaxf(s[t][2], s[t][3]));
        }
        mx0 = fmaxf(mx0, __shfl_xor_sync(0xffffffffu, mx0, 1));
        mx0 = fmaxf(mx0, __shfl_xor_sync(0xffffffffu, mx0, 2));
        mx1 = fmaxf(mx1, __shfl_xor_sync(0xffffffffu, mx1, 1));
        mx1 = fmaxf(mx1, __shfl_xor_sync(0xffffffffu, mx1, 2));
        float mn0 = fmaxf(m0, mx0), mn1 = fmaxf(m1, mx1);
        float a0 = __expf(m0 - mn0), a1 = __expf(m1 - mn1);
        m0 = mn0; m1 = mn1;
        float rs0 = 0.f, rs1 = 0.f;
        #pragma unroll
        for (int t = 0; t < 16; ++t) {
            s[t][0] = __expf(s[t][0] - mn0);
            s[t][1] = __expf(s[t][1] - mn0);
            s[t][2] = __expf(s[t][2] - mn1);
            s[t][3] = __expf(s[t][3] - mn1);
            rs0 += s[t][0] + s[t][1];
            rs1 += s[t][2] + s[t][3];
        }
        #pragma unroll
        for (int t = 0; t < 8; ++t) {
            o[t][0] *= a0; o[t][1] *= a0; o[t][2] *= a1; o[t][3] *= a1;
        }
        rs0 += __shfl_xor_sync(0xffffffffu, rs0, 1);
        rs0 += __shfl_xor_sync(0xffffffffu, rs0, 2);
        rs1 += __shfl_xor_sync(0xffffffffu, rs1, 1);
        rs1 += __shfl_xor_sync(0xffffffffu, rs1, 2);
        l0 = l0 * a0 + rs0;
        l1 = l1 * a1 + rs1;

        // O += P V (single pass)
        #pragma unroll
        for (int kc = 0; kc < 8; ++kc) {
            uint32_t pah[4];
            pah[0] = packh(s[2 * kc][0], s[2 * kc][1]);
            pah[1] = packh(s[2 * kc][2], s[2 * kc][3]);
            pah[2] = packh(s[2 * kc + 1][0], s[2 * kc + 1][1]);
            pah[3] = packh(s[2 * kc + 1][2], s[2 * kc + 1][3]);
            #pragma unroll
            for (int ng = 0; ng < 4; ++ng) {
                uint32_t voff = (kc * 16 + lrow) * TST + ng * 32 + lcol;
                uint32_t vh[4];
                LDSM_X4_T(vh[0], vh[1], vh[2], vh[3], vh_b + voff);
                uint32_t bv0[2] = { vh[0], vh[1] }, bv1[2] = { vh[2], vh[3] };
                MMAH(o[2 * ng],     pah, bv0);
                MMAH(o[2 * ng + 1], pah, bv1);
            }
        }
        __syncthreads();
    }

    // epilogue: O/l -> fp16 at [b*S + q][h*64 + n]
    const float i0 = 1.f / l0, i1 = 1.f / l1;
    const size_t r0 = (size_t)b * Sv + qbase + wq + (lane >> 2);
    const int cb = h * HDv + (lane & 3) * 2;
    #pragma unroll
    for (int t = 0; t < 8; ++t) {
        size_t ia = r0 * Dv + cb + 8 * t;
        size_t ib = ia + (size_t)8 * Dv;
        *(uint32_t*)&oh[ia] = packh(o[t][0] * i0, o[t][1] * i0);
        *(uint32_t*)&oh[ib] = packh(o[t][2] * i1, o[t][3] * i1);
    }
}

// ---------------------------------------------------------------------------
extern "C" void kernel_launch(void* const* d_in, const int* in_sizes, int n_in,
                              void* d_out, int out_size)
{
    (void)in_sizes; (void)n_in; (void)out_size;
    const float* x     = (const float*)d_in[0];
    const float* w_qkv = (const float*)d_in[1];
    const float* w_out = (const float*)d_in[2];
    float* out = (float*)d_out;

    __half *xh, *wq, *qkvh, *oh, *wo;
    cudaGetSymbolAddress((void**)&xh, g_xh);
    cudaGetSymbolAddress((void**)&wq, g_wq);
    cudaGetSymbolAddress((void**)&qkvh, g_qkvh);
    cudaGetSymbolAddress((void**)&oh, g_oh);
    cudaGetSymbolAddress((void**)&wo, g_wo);

    cudaFuncSetAttribute(attn_mma,
                         cudaFuncAttributeMaxDynamicSharedMemorySize, ATTN_SMEM);
    cudaFuncSetAttribute(gemm_mma_h<1>,
                         cudaFuncAttributeMaxDynamicSharedMemorySize, GEMM_SMEM);
    cudaFuncSetAttribute(gemm_mma_h<0>,
                         cudaFuncAttributeMaxDynamicSharedMemorySize, GEMM_SMEM);

    // Conversions (all single fp16)
    {
        int n4 = (Mv * Dv) / 4;
        cvt_h<<<(n4 + 255) / 256, 256>>>(x, xh, n4);
        n4 = (3 * Dv * Dv) / 4;
        cvt_h<<<(n4 + 255) / 256, 256>>>(w_qkv, wq, n4);
        n4 = (Dv * Dv) / 4;
        cvt_h<<<(n4 + 255) / 256, 256>>>(w_out, wo, n4);
    }

    // 1) QKV projection (single-pass fp16, 8 warps/CTA, 3-stage pipe)
    gemm_mma_h<1><<<GEMM_GRID, 256, GEMM_SMEM>>>(
        xh, wq, nullptr, qkvh, Mv, Dv, 3 * Dv);

    // 2) Causal flash attention (1-pass QK, 1-pass PV) -> fp16 O
    {
        dim3 g(Sv / BQa, Hv, Bv);
        attn_mma<<<g, 256, ATTN_SMEM>>>(qkvh, oh);
    }

    // 3) Output projection (single-pass fp16) -> fp32 out
    gemm_mma_h<0><<<GEMM_GRID, 256, GEMM_SMEM>>>(
        oh, wo, out, nullptr, Mv, Dv, Dv);
}

// round 16
// speedup vs baseline: 1.0805x; 1.0805x over previous
#include <cuda_runtime.h>
#include <cuda_fp16.h>
#include <math.h>
#include <stdint.h>

// Problem constants
#define Bv 2
#define Sv 2048
#define Dv 1024
#define Hv 16
#define HDv 64
#define Mv (Bv*Sv)   // 4096 rows

// ---------------------------------------------------------------------------
// Scratch (device globals: no allocation allowed)
// ---------------------------------------------------------------------------
__device__ __align__(16) __half g_xh[(size_t)Mv * Dv];
__device__ __align__(16) __half g_wq[(size_t)3 * Dv * Dv];
__device__ __align__(16) __half g_qkvh[(size_t)Mv * 3 * Dv];
__device__ __align__(16) __half g_oh[(size_t)Mv * Dv];
__device__ __align__(16) __half g_wo[(size_t)Dv * Dv];

// ---------------------------------------------------------------------------
// PTX helpers
// ---------------------------------------------------------------------------
__device__ __forceinline__ uint32_t smem_u32(const void* p) {
    uint32_t a;
    asm("{ .reg .u64 t; cvta.to.shared.u64 t, %1; cvt.u32.u64 %0, t; }" : "=r"(a) : "l"(p));
    return a;
}
#define CP_ASYNC16(sm, g) \
    asm volatile("cp.async.cg.shared.global [%0], [%1], 16;" :: "r"(sm), "l"(g) : "memory")
#define CP_COMMIT() asm volatile("cp.async.commit_group;" ::: "memory")
#define CP_WAIT(n)  asm volatile("cp.async.wait_group %0;" :: "n"(n) : "memory")

#define LDSM_X4(r0, r1, r2, r3, addr) \
    asm volatile("ldmatrix.sync.aligned.m8n8.x4.shared.b16 {%0,%1,%2,%3}, [%4];" \
        : "=r"(r0), "=r"(r1), "=r"(r2), "=r"(r3) : "r"(addr))
#define LDSM_X4_T(r0, r1, r2, r3, addr) \
    asm volatile("ldmatrix.sync.aligned.m8n8.x4.trans.shared.b16 {%0,%1,%2,%3}, [%4];" \
        : "=r"(r0), "=r"(r1), "=r"(r2), "=r"(r3) : "r"(addr))

// fp16 mma, fp32 accumulate
#define MMAH(d, a, b) \
    asm volatile("mma.sync.aligned.m16n8k16.row.col.f32.f16.f16.f32 " \
        "{%0,%1,%2,%3}, {%4,%5,%6,%7}, {%8,%9}, {%0,%1,%2,%3};" \
        : "+f"((d)[0]), "+f"((d)[1]), "+f"((d)[2]), "+f"((d)[3]) \
        : "r"((a)[0]), "r"((a)[1]), "r"((a)[2]), "r"((a)[3]), "r"((b)[0]), "r"((b)[1]))

// pack(lo, hi) -> f16x2 register (lo in low 16 bits)
__device__ __forceinline__ uint32_t packh(float lo, float hi) {
    __half2 h = __floats2half2_rn(lo, hi);
    return *reinterpret_cast<uint32_t*>(&h);
}

// ---------------------------------------------------------------------------
// fp32 -> fp16, three tensors in one launch
// ---------------------------------------------------------------------------
__global__ __launch_bounds__(256) void cvt_h3(
    const float* __restrict__ in0, __half* __restrict__ out0, int n0,
    const float* __restrict__ in1, __half* __restrict__ out1, int n1,
    const float* __restrict__ in2, __half* __restrict__ out2, int n2)
{
    int i = blockIdx.x * blockDim.x + threadIdx.x;
    const float* in; __half* out;
    if (i < n0)            { in = in0; out = out0; }
    else if (i < n0 + n1)  { i -= n0; in = in1; out = out1; }
    else if (i < n0 + n1 + n2) { i -= n0 + n1; in = in2; out = out2; }
    else return;
    float4 v = ((const float4*)in)[i];
    ((uint2*)out)[i] = make_uint2(packh(v.x, v.y), packh(v.z, v.w));
}

// ---------------------------------------------------------------------------
// Persistent single-pass fp16 GEMM:  C[M,N] = A[M,K] * B[N,K]^T
// 128x128x32 CTA tile, 128 threads = 4 warps (64x64 each).
// 4-stage cp.async pipeline, 2 CTAs/SM.
// WB=1: write fp16; WB=0: write fp32.
// ---------------------------------------------------------------------------
#define BM 128
#define BN 128
#define BKc 32
#define TILE_BYT (128 * 80)           // 80B row stride
#define STAGE_BYT (2 * TILE_BYT)      // A, B
#define NSTG 4
#define GEMM_SMEM (NSTG * STAGE_BYT)  // 81920 B
#define GEMM_GRID 296

__device__ __forceinline__ void load_stage(
    uint32_t sb, int s,
    const __half* __restrict__ A, const __half* __restrict__ B,
    int bm, int bn, int k0, int K, int tid)
{
    uint32_t base = sb + s * STAGE_BYT;
    #pragma unroll
    for (int j = 0; j < 4; ++j) {
        int idx = tid + j * 128;            // 0..511
        int row = idx >> 2, ch = idx & 3;
        CP_ASYNC16(base + row * 80 + ch * 16,
                   A + (size_t)(bm + row) * K + k0 + ch * 8);
        CP_ASYNC16(base + TILE_BYT + row * 80 + ch * 16,
                   B + (size_t)(bn + row) * K + k0 + ch * 8);
    }
}

template<int WB>
__global__ __launch_bounds__(128) void gemm_mma_h(
    const __half* __restrict__ A, const __half* __restrict__ B,
    float* __restrict__ C, __half* __restrict__ Ch, int M, int K, int N)
{
    extern __shared__ char smem[];
    const uint32_t sb = smem_u32(smem);
    const int tid = threadIdx.x, wid = tid >> 5, lane = tid & 31;
    const int wm = (wid >> 1) * 64;
    const int wn = (wid & 1) * 64;
    const uint32_t lrow = (lane & 15);
    const uint32_t lcol = (lane >> 4) * 16;
    const int ntn = N / BN;
    const int ntot = (M / BM) * ntn;
    const int NKB = K / BKc;              // 32

    for (int tix = blockIdx.x; tix < ntot; tix += (int)gridDim.x) {
        const int bm = (tix / ntn) * BM, bn = (tix % ntn) * BN;

        float acc[4][8][4];
        #pragma unroll
        for (int i = 0; i < 4; ++i)
            #pragma unroll
            for (int j = 0; j < 8; ++j)
                #pragma unroll
                for (int q = 0; q < 4; ++q) acc[i][j][q] = 0.f;

        #pragma unroll
        for (int p = 0; p < NSTG - 1; ++p) {
            load_stage(sb, p, A, B, bm, bn, p * BKc, K, tid);
            CP_COMMIT();
        }

        for (int kb = 0; kb < NKB; ++kb) {
            const int s = kb % NSTG;
            if (kb + NSTG - 1 < NKB) {
                load_stage(sb, (kb + NSTG - 1) % NSTG, A, B, bm, bn,
                           (kb + NSTG - 1) * BKc, K, tid);
                CP_COMMIT();
            }
            // wait until stage kb's group has landed
            {
                int pend = NKB - 1 - kb;                    // groups issued after kb's
                int mx = NSTG - 1;
                int w = pend < mx ? pend : mx;
                if (w >= 3)      CP_WAIT(3);
                else if (w == 2) CP_WAIT(2);
                else if (w == 1) CP_WAIT(1);
                else             CP_WAIT(0);
            }
            __syncthreads();

            const uint32_t stb = sb + s * STAGE_BYT;
            #pragma unroll
            for (int ks = 0; ks < 2; ++ks) {
                const uint32_t koff = ks * 32 + lcol;
                uint32_t aa[4][4], bb[4][4];
                #pragma unroll
                for (int rt = 0; rt < 4; ++rt) {
                    uint32_t ro = (wm + rt * 16 + lrow) * 80 + koff;
                    LDSM_X4(aa[rt][0], aa[rt][1], aa[rt][2], aa[rt][3], stb + ro);
                }
                #pragma unroll
                for (int g = 0; g < 4; ++g) {
                    uint32_t ro = (wn + g * 16 + lrow) * 80 + koff;
                    LDSM_X4(bb[g][0], bb[g][1], bb[g][2], bb[g][3], stb + TILE_BYT + ro);
                }
                #pragma unroll
                for (int rt = 0; rt < 4; ++rt)
                    #pragma unroll
                    for (int g = 0; g < 4; ++g)
                        #pragma unroll
                        for (int sub = 0; sub < 2; ++sub) {
                            uint32_t bf[2] = { bb[g][sub], bb[g][sub + 2] };
                            MMAH(acc[rt][g * 2 + sub], aa[rt], bf);
                        }
            }
            __syncthreads();
        }

        const int r0 = bm + wm + (lane >> 2);
        const int c0 = bn + wn + (lane & 3) * 2;
        #pragma unroll
        for (int rt = 0; rt < 4; ++rt)
            #pragma unroll
            for (int ct = 0; ct < 8; ++ct) {
                size_t i0 = (size_t)(r0 + rt * 16) * N + c0 + ct * 8;
                size_t i1 = i0 + (size_t)8 * N;
                if (WB) {
                    *(uint32_t*)&Ch[i0] = packh(acc[rt][ct][0], acc[rt][ct][1]);
                    *(uint32_t*)&Ch[i1] = packh(acc[rt][ct][2], acc[rt][ct][3]);
                } else {
                    *(float2*)&C[i0] = make_float2(acc[rt][ct][0], acc[rt][ct][1]);
                    *(float2*)&C[i1] = make_float2(acc[rt][ct][2], acc[rt][ct][3]);
                }
            }
    }
}

// ---------------------------------------------------------------------------
// Flash attention, all single-pass fp16. CTA: 128 q-rows x 128 kv tile.
//   S = Qh*Kh ; O = Ph*Vh
// ---------------------------------------------------------------------------
#define BQa 128
#define BKVa 128
#define TST 144
#define SQH 0
#define KVB (128 * TST)
#define KVSTG (2 * 128 * TST)           // Kh + Vh
#define ATTN_SMEM (KVB + 2 * KVSTG)     // 92160 B

__global__ __launch_bounds__(256) void attn_mma(
    const __half* __restrict__ qkvh, __half* __restrict__ oh)
{
    extern __shared__ char smem[];
    const uint32_t sb = smem_u32(smem);
    const int tid = threadIdx.x, wid = tid >> 5, lane = tid & 31;
    const int qi = (int)gridDim.x - 1 - (int)blockIdx.x;   // heavy tiles first
    const int h = blockIdx.y, b = blockIdx.z;
    const int qbase = qi * BQa;
    const int wq = wid * 16;
    const uint32_t lrow = lane & 15, lcol = (lane >> 4) * 16;
    const size_t ld = 3 * Dv;

    // Load Q tile
    {
        const size_t base = ((size_t)b * Sv + qbase) * ld + (size_t)h * HDv;
        #pragma unroll
        for (int i = 0; i < 4; ++i) {
            int idx = tid + i * 256;            // 128 rows * 8 chunks
            int rr = (idx >> 3) & 127, ch = idx & 7;
            CP_ASYNC16(sb + SQH + rr * TST + ch * 16,
                       qkvh + base + (size_t)rr * ld + ch * 8);
        }
    }

    const int ntiles = qi + 1;
    // prologue: KV tile 0 -> stage 0 (Kh, Vh)
    {
        const size_t kbase = ((size_t)b * Sv) * ld + Dv + (size_t)h * HDv;
        #pragma unroll
        for (int i = 0; i < 8; ++i) {
            int idx = tid + i * 256;
            int t = idx >> 10, rr = (idx >> 3) & 127, ch = idx & 7;
            const __half* src = qkvh + kbase + (t ? Dv : 0) + (size_t)rr * ld + ch * 8;
            CP_ASYNC16(sb + KVB + t * (128 * TST) + rr * TST + ch * 16, src);
        }
    }
    CP_COMMIT();

    float s[16][4], o[8][4];
    #pragma unroll
    for (int t = 0; t < 8; ++t)
        #pragma unroll
        for (int e = 0; e < 4; ++e) o[t][e] = 0.f;
    float m0 = -1e30f, m1 = -1e30f, l0 = 0.f, l1 = 0.f;

    for (int j = 0; j < ntiles; ++j) {
        const int stg = j & 1;
        if (j + 1 < ntiles) {
            const size_t kbase = ((size_t)b * Sv + (size_t)(j + 1) * BKVa) * ld + Dv + (size_t)h * HDv;
            uint32_t s0 = sb + KVB + (stg ^ 1) * KVSTG;
            #pragma unroll
            for (int i = 0; i < 8; ++i) {
                int idx = tid + i * 256;
                int t = idx >> 10, rr = (idx >> 3) & 127, ch = idx & 7;
                const __half* src = qkvh + kbase + (t ? Dv : 0) + (size_t)rr * ld + ch * 8;
                CP_ASYNC16(s0 + t * (128 * TST) + rr * TST + ch * 16, src);
            }
            CP_COMMIT();
            CP_WAIT(1);
        } else {
            CP_WAIT(0);
        }
        __syncthreads();

        const uint32_t kh_b = sb + KVB + stg * KVSTG;
        const uint32_t vh_b = kh_b + 128 * TST;

        // S = Q K^T (single pass), 16 n8-tiles
        #pragma unroll
        for (int t = 0; t < 16; ++t)
            #pragma unroll
            for (int e = 0; e < 4; ++e) s[t][e] = 0.f;
        #pragma unroll
        for (int dc = 0; dc < 4; ++dc) {
            uint32_t qoff = (wq + lrow) * TST + dc * 32 + lcol;
            uint32_t qh[4];
            LDSM_X4(qh[0], qh[1], qh[2], qh[3], sb + SQH + qoff);
            #pragma unroll
            for (int ng = 0; ng < 8; ++ng) {
                uint32_t koff = (ng * 16 + lrow) * TST + dc * 32 + lcol;
                uint32_t kh[4];
                LDSM_X4(kh[0], kh[1], kh[2], kh[3], kh_b + koff);
                uint32_t b0h[2] = { kh[0], kh[2] }, b1h[2] = { kh[1], kh[3] };
                MMAH(s[2 * ng],     qh, b0h);
                MMAH(s[2 * ng + 1], qh, b1h);
            }
        }

        // scale + causal mask (diagonal tile only)
        const int row0 = qbase + wq + (lane >> 2);
        if (j == ntiles - 1) {
            #pragma unroll
            for (int t = 0; t < 16; ++t) {
                int colb = j * BKVa + 8 * t + (lane & 3) * 2;
                #pragma unroll
                for (int e = 0; e < 4; ++e) {
                    int col = colb + (e & 1);
                    int row = (e < 2) ? row0 : row0 + 8;
                    s[t][e] = (col > row) ? -1e30f : s[t][e] * 0.125f;
                }
            }
        } else {
            #pragma unroll
            for (int t = 0; t < 16; ++t)
                #pragma unroll
                for (int e = 0; e < 4; ++e) s[t][e] *= 0.125f;
        }

        // online softmax
        float mx0 = -1e30f, mx1 = -1e30f;
        #pragma unroll
        for (int t = 0; t < 16; ++t) {
            mx0 = fmaxf(mx0, fmaxf(s[t][0], s[t][1]));
            mx1 = fmaxf(mx1, fmaxf(s[t][2], s[t][3]));
        }
        mx0 = fmaxf(mx0, __shfl_xor_sync(0xffffffffu, mx0, 1));
        mx0 = fmaxf(mx0, __shfl_xor_sync(0xffffffffu, mx0, 2));
        mx1 = fmaxf(mx1, __shfl_xor_sync(0xffffffffu, mx1, 1));
        mx1 = fmaxf(mx1, __shfl_xor_sync(0xffffffffu, mx1, 2));
        float mn0 = fmaxf(m0, mx0), mn1 = fmaxf(m1, mx1);
        float a0 = __expf(m0 - mn0), a1 = __expf(m1 - mn1);
        m0 = mn0; m1 = mn1;
        float rs0 = 0.f, rs1 = 0.f;
        #pragma unroll
        for (int t = 0; t < 16; ++t) {
            s[t][0] = __expf(s[t][0] - mn0);
            s[t][1] = __expf(s[t][1] - mn0);
            s[t][2] = __expf(s[t][2] - mn1);
            s[t][3] = __expf(s[t][3] - mn1);
            rs0 += s[t][0] + s[t][1];
            rs1 += s[t][2] + s[t][3];
        }
        #pragma unroll
        for (int t = 0; t < 8; ++t) {
            o[t][0] *= a0; o[t][1] *= a0; o[t][2] *= a1; o[t][3] *= a1;
        }
        rs0 += __shfl_xor_sync(0xffffffffu, rs0, 1);
        rs0 += __shfl_xor_sync(0xffffffffu, rs0, 2);
        rs1 += __shfl_xor_sync(0xffffffffu, rs1, 1);
        rs1 += __shfl_xor_sync(0xffffffffu, rs1, 2);
        l0 = l0 * a0 + rs0;
        l1 = l1 * a1 + rs1;

        // O += P V (single pass)
        #pragma unroll
        for (int kc = 0; kc < 8; ++kc) {
            uint32_t pah[4];
            pah[0] = packh(s[2 * kc][0], s[2 * kc][1]);
            pah[1] = packh(s[2 * kc][2], s[2 * kc][3]);
            pah[2] = packh(s[2 * kc + 1][0], s[2 * kc + 1][1]);
            pah[3] = packh(s[2 * kc + 1][2], s[2 * kc + 1][3]);
            #pragma unroll
            for (int ng = 0; ng < 4; ++ng) {
                uint32_t voff = (kc * 16 + lrow) * TST + ng * 32 + lcol;
                uint32_t vh[4];
                LDSM_X4_T(vh[0], vh[1], vh[2], vh[3], vh_b + voff);
                uint32_t bv0[2] = { vh[0], vh[1] }, bv1[2] = { vh[2], vh[3] };
                MMAH(o[2 * ng],     pah, bv0);
                MMAH(o[2 * ng + 1], pah, bv1);
            }
        }
        __syncthreads();
    }

    // epilogue: O/l -> fp16 at [b*S + q][h*64 + n]
    const float i0 = 1.f / l0, i1 = 1.f / l1;
    const size_t r0 = (size_t)b * Sv + qbase + wq + (lane >> 2);
    const int cb = h * HDv + (lane & 3) * 2;
    #pragma unroll
    for (int t = 0; t < 8; ++t) {
        size_t ia = r0 * Dv + cb + 8 * t;
        size_t ib = ia + (size_t)8 * Dv;
        *(uint32_t*)&oh[ia] = packh(o[t][0] * i0, o[t][1] * i0);
        *(uint32_t*)&oh[ib] = packh(o[t][2] * i1, o[t][3] * i1);
    }
}

// ---------------------------------------------------------------------------
extern "C" void kernel_launch(void* const* d_in, const int* in_sizes, int n_in,
                              void* d_out, int out_size)
{
    (void)in_sizes; (void)n_in; (void)out_size;
    const float* x     = (const float*)d_in[0];
    const float* w_qkv = (const float*)d_in[1];
    const float* w_out = (const float*)d_in[2];
    float* out = (float*)d_out;

    __half *xh, *wq, *qkvh, *oh, *wo;
    cudaGetSymbolAddress((void**)&xh, g_xh);
    cudaGetSymbolAddress((void**)&wq, g_wq);
    cudaGetSymbolAddress((void**)&qkvh, g_qkvh);
    cudaGetSymbolAddress((void**)&oh, g_oh);
    cudaGetSymbolAddress((void**)&wo, g_wo);

    cudaFuncSetAttribute(attn_mma,
                         cudaFuncAttributeMaxDynamicSharedMemorySize, ATTN_SMEM);
    cudaFuncSetAttribute(gemm_mma_h<1>,
                         cudaFuncAttributeMaxDynamicSharedMemorySize, GEMM_SMEM);
    cudaFuncSetAttribute(gemm_mma_h<0>,
                         cudaFuncAttributeMaxDynamicSharedMemorySize, GEMM_SMEM);

    // Conversions (all three tensors in one launch)
    {
        int n0 = (Mv * Dv) / 4;
        int n1 = (3 * Dv * Dv) / 4;
        int n2 = (Dv * Dv) / 4;
        int tot = n0 + n1 + n2;
        cvt_h3<<<(tot + 255) / 256, 256>>>(x, xh, n0, w_qkv, wq, n1, w_out, wo, n2);
    }

    // 1) QKV projection (single-pass fp16, 4-stage pipe) -> fp16 qkv
    gemm_mma_h<1><<<GEMM_GRID, 128, GEMM_SMEM>>>(
        xh, wq, nullptr, qkvh, Mv, Dv, 3 * Dv);

    // 2) Causal flash attention (1-pass QK, 1-pass PV) -> fp16 O
    {
        dim3 g(Sv / BQa, Hv, Bv);
        attn_mma<<<g, 256, ATTN_SMEM>>>(qkvh, oh);
    }

    // 3) Output projection (single-pass fp16) -> fp32 out
    gemm_mma_h<0><<<GEMM_GRID, 128, GEMM_SMEM>>>(
        oh, wo, out, nullptr, Mv, Dv, Dv);
}

// round 17
// speedup vs baseline: 1.0996x; 1.0177x over previous
#include <cuda_runtime.h>
#include <cuda_fp16.h>
#include <math.h>
#include <stdint.h>

// Problem constants
#define Bv 2
#define Sv 2048
#define Dv 1024
#define Hv 16
#define HDv 64
#define Mv (Bv*Sv)   // 4096 rows

// ---------------------------------------------------------------------------
// Scratch (device globals: no allocation allowed)
// ---------------------------------------------------------------------------
__device__ __align__(16) __half g_xh[(size_t)Mv * Dv];
__device__ __align__(16) __half g_wq[(size_t)3 * Dv * Dv];
__device__ __align__(16) __half g_qkvh[(size_t)Mv * 3 * Dv];
__device__ __align__(16) __half g_oh[(size_t)Mv * Dv];
__device__ __align__(16) __half g_wo[(size_t)Dv * Dv];

// ---------------------------------------------------------------------------
// PTX helpers
// ---------------------------------------------------------------------------
__device__ __forceinline__ uint32_t smem_u32(const void* p) {
    uint32_t a;
    asm("{ .reg .u64 t; cvta.to.shared.u64 t, %1; cvt.u32.u64 %0, t; }" : "=r"(a) : "l"(p));
    return a;
}
#define CP_ASYNC16(sm, g) \
    asm volatile("cp.async.cg.shared.global [%0], [%1], 16;" :: "r"(sm), "l"(g) : "memory")
#define CP_COMMIT() asm volatile("cp.async.commit_group;" ::: "memory")
#define CP_WAIT(n)  asm volatile("cp.async.wait_group %0;" :: "n"(n) : "memory")

#define LDSM_X4(r0, r1, r2, r3, addr) \
    asm volatile("ldmatrix.sync.aligned.m8n8.x4.shared.b16 {%0,%1,%2,%3}, [%4];" \
        : "=r"(r0), "=r"(r1), "=r"(r2), "=r"(r3) : "r"(addr))
#define LDSM_X4_T(r0, r1, r2, r3, addr) \
    asm volatile("ldmatrix.sync.aligned.m8n8.x4.trans.shared.b16 {%0,%1,%2,%3}, [%4];" \
        : "=r"(r0), "=r"(r1), "=r"(r2), "=r"(r3) : "r"(addr))

// fp16 mma, fp32 accumulate
#define MMAH(d, a, b) \
    asm volatile("mma.sync.aligned.m16n8k16.row.col.f32.f16.f16.f32 " \
        "{%0,%1,%2,%3}, {%4,%5,%6,%7}, {%8,%9}, {%0,%1,%2,%3};" \
        : "+f"((d)[0]), "+f"((d)[1]), "+f"((d)[2]), "+f"((d)[3]) \
        : "r"((a)[0]), "r"((a)[1]), "r"((a)[2]), "r"((a)[3]), "r"((b)[0]), "r"((b)[1]))

// pack(lo, hi) -> f16x2 register (lo in low 16 bits)
__device__ __forceinline__ uint32_t packh(float lo, float hi) {
    __half2 h = __floats2half2_rn(lo, hi);
    return *reinterpret_cast<uint32_t*>(&h);
}

// ---------------------------------------------------------------------------
// fp32 -> fp16, three tensors in one launch
// ---------------------------------------------------------------------------
__global__ __launch_bounds__(256) void cvt_h3(
    const float* __restrict__ in0, __half* __restrict__ out0, int n0,
    const float* __restrict__ in1, __half* __restrict__ out1, int n1,
    const float* __restrict__ in2, __half* __restrict__ out2, int n2)
{
    int i = blockIdx.x * blockDim.x + threadIdx.x;
    const float* in; __half* out;
    if (i < n0)            { in = in0; out = out0; }
    else if (i < n0 + n1)  { i -= n0; in = in1; out = out1; }
    else if (i < n0 + n1 + n2) { i -= n0 + n1; in = in2; out = out2; }
    else return;
    float4 v = ((const float4*)in)[i];
    ((uint2*)out)[i] = make_uint2(packh(v.x, v.y), packh(v.z, v.w));
}

// ---------------------------------------------------------------------------
// Persistent single-pass fp16 GEMM:  C[M,N] = A[M,K] * B[N,K]^T
// 128x128x32 CTA tile, 128 threads = 4 warps (64x64 each).
// 4-stage cp.async pipeline, ONE barrier per iteration:
//   wait(stage k) -> sync -> prefetch(k+3) -> mma(stage k)
// The barrier both publishes stage k and retires reads of the stage that
// the new prefetch overwrites (read at iteration k-1).
// ---------------------------------------------------------------------------
#define BM 128
#define BN 128
#define BKc 32
#define TILE_BYT (128 * 80)           // 80B row stride
#define STAGE_BYT (2 * TILE_BYT)      // A, B
#define NSTG 4
#define GEMM_SMEM (NSTG * STAGE_BYT)  // 81920 B
#define GEMM_GRID 296

__device__ __forceinline__ void load_stage(
    uint32_t sb, int s,
    const __half* __restrict__ A, const __half* __restrict__ B,
    int bm, int bn, int k0, int K, int tid)
{
    uint32_t base = sb + s * STAGE_BYT;
    #pragma unroll
    for (int j = 0; j < 4; ++j) {
        int idx = tid + j * 128;            // 0..511
        int row = idx >> 2, ch = idx & 3;
        CP_ASYNC16(base + row * 80 + ch * 16,
                   A + (size_t)(bm + row) * K + k0 + ch * 8);
        CP_ASYNC16(base + TILE_BYT + row * 80 + ch * 16,
                   B + (size_t)(bn + row) * K + k0 + ch * 8);
    }
}

template<int WB>
__global__ __launch_bounds__(128) void gemm_mma_h(
    const __half* __restrict__ A, const __half* __restrict__ B,
    float* __restrict__ C, __half* __restrict__ Ch, int M, int K, int N)
{
    extern __shared__ char smem[];
    const uint32_t sb = smem_u32(smem);
    const int tid = threadIdx.x, wid = tid >> 5, lane = tid & 31;
    const int wm = (wid >> 1) * 64;
    const int wn = (wid & 1) * 64;
    const uint32_t lrow = (lane & 15);
    const uint32_t lcol = (lane >> 4) * 16;
    const int ntn = N / BN;
    const int ntot = (M / BM) * ntn;
    const int NKB = K / BKc;              // 32

    for (int tix = blockIdx.x; tix < ntot; tix += (int)gridDim.x) {
        const int bm = (tix / ntn) * BM, bn = (tix % ntn) * BN;

        float acc[4][8][4];
        #pragma unroll
        for (int i = 0; i < 4; ++i)
            #pragma unroll
            for (int j = 0; j < 8; ++j)
                #pragma unroll
                for (int q = 0; q < 4; ++q) acc[i][j][q] = 0.f;

        #pragma unroll
        for (int p = 0; p < NSTG - 1; ++p) {
            load_stage(sb, p, A, B, bm, bn, p * BKc, K, tid);
            CP_COMMIT();
        }

        for (int kb = 0; kb < NKB; ++kb) {
            const int s = kb % NSTG;
            // wait until stage kb's group has landed (prefetch for kb+3 not
            // yet committed here, so steady-state pending beyond kb is 2)
            {
                int w = NKB - 1 - kb;
                if (w > NSTG - 2) w = NSTG - 2;
                if (w >= 2)      CP_WAIT(2);
                else if (w == 1) CP_WAIT(1);
                else             CP_WAIT(0);
            }
            __syncthreads();

            if (kb + NSTG - 1 < NKB) {
                load_stage(sb, (kb + NSTG - 1) % NSTG, A, B, bm, bn,
                           (kb + NSTG - 1) * BKc, K, tid);
                CP_COMMIT();
            }

            const uint32_t stb = sb + s * STAGE_BYT;
            #pragma unroll
            for (int ks = 0; ks < 2; ++ks) {
                const uint32_t koff = ks * 32 + lcol;
                uint32_t aa[4][4], bb[4][4];
                #pragma unroll
                for (int rt = 0; rt < 4; ++rt) {
                    uint32_t ro = (wm + rt * 16 + lrow) * 80 + koff;
                    LDSM_X4(aa[rt][0], aa[rt][1], aa[rt][2], aa[rt][3], stb + ro);
                }
                #pragma unroll
                for (int g = 0; g < 4; ++g) {
                    uint32_t ro = (wn + g * 16 + lrow) * 80 + koff;
                    LDSM_X4(bb[g][0], bb[g][1], bb[g][2], bb[g][3], stb + TILE_BYT + ro);
                }
                #pragma unroll
                for (int rt = 0; rt < 4; ++rt)
                    #pragma unroll
                    for (int g = 0; g < 4; ++g)
                        #pragma unroll
                        for (int sub = 0; sub < 2; ++sub) {
                            uint32_t bf[2] = { bb[g][sub], bb[g][sub + 2] };
                            MMAH(acc[rt][g * 2 + sub], aa[rt], bf);
                        }
            }
        }
        __syncthreads();   // retire last stage's reads before next tile reuses smem

        const int r0 = bm + wm + (lane >> 2);
        const int c0 = bn + wn + (lane & 3) * 2;
        #pragma unroll
        for (int rt = 0; rt < 4; ++rt)
            #pragma unroll
            for (int ct = 0; ct < 8; ++ct) {
                size_t i0 = (size_t)(r0 + rt * 16) * N + c0 + ct * 8;
                size_t i1 = i0 + (size_t)8 * N;
                if (WB) {
                    *(uint32_t*)&Ch[i0] = packh(acc[rt][ct][0], acc[rt][ct][1]);
                    *(uint32_t*)&Ch[i1] = packh(acc[rt][ct][2], acc[rt][ct][3]);
                } else {
                    *(float2*)&C[i0] = make_float2(acc[rt][ct][0], acc[rt][ct][1]);
                    *(float2*)&C[i1] = make_float2(acc[rt][ct][2], acc[rt][ct][3]);
                }
            }
    }
}

// ---------------------------------------------------------------------------
// Flash attention, all single-pass fp16. CTA: 128 q-rows x 128 kv tile.
//   S = Qh*Kh ; O = Ph*Vh
// Single barrier per kv tile: wait(tile j) -> sync -> prefetch(j+1) -> compute.
// ---------------------------------------------------------------------------
#define BQa 128
#define BKVa 128
#define TST 144
#define SQH 0
#define KVB (128 * TST)
#define KVSTG (2 * 128 * TST)           // Kh + Vh
#define ATTN_SMEM (KVB + 2 * KVSTG)     // 92160 B

__global__ __launch_bounds__(256) void attn_mma(
    const __half* __restrict__ qkvh, __half* __restrict__ oh)
{
    extern __shared__ char smem[];
    const uint32_t sb = smem_u32(smem);
    const int tid = threadIdx.x, wid = tid >> 5, lane = tid & 31;
    const int qi = (int)gridDim.x - 1 - (int)blockIdx.x;   // heavy tiles first
    const int h = blockIdx.y, b = blockIdx.z;
    const int qbase = qi * BQa;
    const int wq = wid * 16;
    const uint32_t lrow = lane & 15, lcol = (lane >> 4) * 16;
    const size_t ld = 3 * Dv;

    // Load Q tile
    {
        const size_t base = ((size_t)b * Sv + qbase) * ld + (size_t)h * HDv;
        #pragma unroll
        for (int i = 0; i < 4; ++i) {
            int idx = tid + i * 256;            // 128 rows * 8 chunks
            int rr = (idx >> 3) & 127, ch = idx & 7;
            CP_ASYNC16(sb + SQH + rr * TST + ch * 16,
                       qkvh + base + (size_t)rr * ld + ch * 8);
        }
    }

    const int ntiles = qi + 1;
    // prologue: KV tile 0 -> stage 0 (Kh, Vh)
    {
        const size_t kbase = ((size_t)b * Sv) * ld + Dv + (size_t)h * HDv;
        #pragma unroll
        for (int i = 0; i < 8; ++i) {
            int idx = tid + i * 256;
            int t = idx >> 10, rr = (idx >> 3) & 127, ch = idx & 7;
            const __half* src = qkvh + kbase + (t ? Dv : 0) + (size_t)rr * ld + ch * 8;
            CP_ASYNC16(sb + KVB + t * (128 * TST) + rr * TST + ch * 16, src);
        }
    }
    CP_COMMIT();

    float s[16][4], o[8][4];
    #pragma unroll
    for (int t = 0; t < 8; ++t)
        #pragma unroll
        for (int e = 0; e < 4; ++e) o[t][e] = 0.f;
    float m0 = -1e30f, m1 = -1e30f, l0 = 0.f, l1 = 0.f;

    for (int j = 0; j < ntiles; ++j) {
        const int stg = j & 1;
        CP_WAIT(0);        // tile j (committed a full iteration ago) landed
        __syncthreads();   // publish tile j; retire reads of stage stg^1

        if (j + 1 < ntiles) {
            const size_t kbase = ((size_t)b * Sv + (size_t)(j + 1) * BKVa) * ld + Dv + (size_t)h * HDv;
            uint32_t s0 = sb + KVB + (stg ^ 1) * KVSTG;
            #pragma unroll
            for (int i = 0; i < 8; ++i) {
                int idx = tid + i * 256;
                int t = idx >> 10, rr = (idx >> 3) & 127, ch = idx & 7;
                const __half* src = qkvh + kbase + (t ? Dv : 0) + (size_t)rr * ld + ch * 8;
                CP_ASYNC16(s0 + t * (128 * TST) + rr * TST + ch * 16, src);
            }
            CP_COMMIT();
        }

        const uint32_t kh_b = sb + KVB + stg * KVSTG;
        const uint32_t vh_b = kh_b + 128 * TST;

        // S = Q K^T (single pass), 16 n8-tiles
        #pragma unroll
        for (int t = 0; t < 16; ++t)
            #pragma unroll
            for (int e = 0; e < 4; ++e) s[t][e] = 0.f;
        #pragma unroll
        for (int dc = 0; dc < 4; ++dc) {
            uint32_t qoff = (wq + lrow) * TST + dc * 32 + lcol;
            uint32_t qh[4];
            LDSM_X4(qh[0], qh[1], qh[2], qh[3], sb + SQH + qoff);
            #pragma unroll
            for (int ng = 0; ng < 8; ++ng) {
                uint32_t koff = (ng * 16 + lrow) * TST + dc * 32 + lcol;
                uint32_t kh[4];
                LDSM_X4(kh[0], kh[1], kh[2], kh[3], kh_b + koff);
                uint32_t b0h[2] = { kh[0], kh[2] }, b1h[2] = { kh[1], kh[3] };
                MMAH(s[2 * ng],     qh, b0h);
                MMAH(s[2 * ng + 1], qh, b1h);
            }
        }

        // scale + causal mask (diagonal tile only)
        const int row0 = qbase + wq + (lane >> 2);
        if (j == ntiles - 1) {
            #pragma unroll
            for (int t = 0; t < 16; ++t) {
                int colb = j * BKVa + 8 * t + (lane & 3) * 2;
                #pragma unroll
                for (int e = 0; e < 4; ++e) {
                    int col = colb + (e & 1);
                    int row = (e < 2) ? row0 : row0 + 8;
                    s[t][e] = (col > row) ? -1e30f : s[t][e] * 0.125f;
                }
            }
        } else {
            #pragma unroll
            for (int t = 0; t < 16; ++t)
                #pragma unroll
                for (int e = 0; e < 4; ++e) s[t][e] *= 0.125f;
        }

        // online softmax
        float mx0 = -1e30f, mx1 = -1e30f;
        #pragma unroll
        for (int t = 0; t < 16; ++t) {
            mx0 = fmaxf(mx0, fmaxf(s[t][0], s[t][1]));
            mx1 = fmaxf(mx1, fmaxf(s[t][2], s[t][3]));
        }
        mx0 = fmaxf(mx0, __shfl_xor_sync(0xffffffffu, mx0, 1));
        mx0 = fmaxf(mx0, __shfl_xor_sync(0xffffffffu, mx0, 2));
        mx1 = fmaxf(mx1, __shfl_xor_sync(0xffffffffu, mx1, 1));
        mx1 = fmaxf(mx1, __shfl_xor_sync(0xffffffffu, mx1, 2));
        float mn0 = fmaxf(m0, mx0), mn1 = fmaxf(m1, mx1);
        float a0 = __expf(m0 - mn0), a1 = __expf(m1 - mn1);
        m0 = mn0; m1 = mn1;
        float rs0 = 0.f, rs1 = 0.f;
        #pragma unroll
        for (int t = 0; t < 16; ++t) {
            s[t][0] = __expf(s[t][0] - mn0);
            s[t][1] = __expf(s[t][1] - mn0);
            s[t][2] = __expf(s[t][2] - mn1);
            s[t][3] = __expf(s[t][3] - mn1);
            rs0 += s[t][0] + s[t][1];
            rs1 += s[t][2] + s[t][3];
        }
        #pragma unroll
        for (int t = 0; t < 8; ++t) {
            o[t][0] *= a0; o[t][1] *= a0; o[t][2] *= a1; o[t][3] *= a1;
        }
        rs0 += __shfl_xor_sync(0xffffffffu, rs0, 1);
        rs0 += __shfl_xor_sync(0xffffffffu, rs0, 2);
        rs1 += __shfl_xor_sync(0xffffffffu, rs1, 1);
        rs1 += __shfl_xor_sync(0xffffffffu, rs1, 2);
        l0 = l0 * a0 + rs0;
        l1 = l1 * a1 + rs1;

        // O += P V (single pass)
        #pragma unroll
        for (int kc = 0; kc < 8; ++kc) {
            uint32_t pah[4];
            pah[0] = packh(s[2 * kc][0], s[2 * kc][1]);
            pah[1] = packh(s[2 * kc][2], s[2 * kc][3]);
            pah[2] = packh(s[2 * kc + 1][0], s[2 * kc + 1][1]);
            pah[3] = packh(s[2 * kc + 1][2], s[2 * kc + 1][3]);
            #pragma unroll
            for (int ng = 0; ng < 4; ++ng) {
                uint32_t voff = (kc * 16 + lrow) * TST + ng * 32 + lcol;
                uint32_t vh[4];
                LDSM_X4_T(vh[0], vh[1], vh[2], vh[3], vh_b + voff);
                uint32_t bv0[2] = { vh[0], vh[1] }, bv1[2] = { vh[2], vh[3] };
                MMAH(o[2 * ng],     pah, bv0);
                MMAH(o[2 * ng + 1], pah, bv1);
            }
        }
    }

    // epilogue: O/l -> fp16 at [b*S + q][h*64 + n]
    const float i0 = 1.f / l0, i1 = 1.f / l1;
    const size_t r0 = (size_t)b * Sv + qbase + wq + (lane >> 2);
    const int cb = h * HDv + (lane & 3) * 2;
    #pragma unroll
    for (int t = 0; t < 8; ++t) {
        size_t ia = r0 * Dv + cb + 8 * t;
        size_t ib = ia + (size_t)8 * Dv;
        *(uint32_t*)&oh[ia] = packh(o[t][0] * i0, o[t][1] * i0);
        *(uint32_t*)&oh[ib] = packh(o[t][2] * i1, o[t][3] * i1);
    }
}

// ---------------------------------------------------------------------------
extern "C" void kernel_launch(void* const* d_in, const int* in_sizes, int n_in,
                              void* d_out, int out_size)
{
    (void)in_sizes; (void)n_in; (void)out_size;
    const float* x     = (const float*)d_in[0];
    const float* w_qkv = (const float*)d_in[1];
    const float* w_out = (const float*)d_in[2];
    float* out = (float*)d_out;

    __half *xh, *wq, *qkvh, *oh, *wo;
    cudaGetSymbolAddress((void**)&xh, g_xh);
    cudaGetSymbolAddress((void**)&wq, g_wq);
    cudaGetSymbolAddress((void**)&qkvh, g_qkvh);
    cudaGetSymbolAddress((void**)&oh, g_oh);
    cudaGetSymbolAddress((void**)&wo, g_wo);

    cudaFuncSetAttribute(attn_mma,
                         cudaFuncAttributeMaxDynamicSharedMemorySize, ATTN_SMEM);
    cudaFuncSetAttribute(gemm_mma_h<1>,
                         cudaFuncAttributeMaxDynamicSharedMemorySize, GEMM_SMEM);
    cudaFuncSetAttribute(gemm_mma_h<0>,
                         cudaFuncAttributeMaxDynamicSharedMemorySize, GEMM_SMEM);

    // Conversions (all three tensors in one launch)
    {
        int n0 = (Mv * Dv) / 4;
        int n1 = (3 * Dv * Dv) / 4;
        int n2 = (Dv * Dv) / 4;
        int tot = n0 + n1 + n2;
        cvt_h3<<<(tot + 255) / 256, 256>>>(x, xh, n0, w_qkv, wq, n1, w_out, wo, n2);
    }

    // 1) QKV projection (single-pass fp16, 4-stage pipe, 1 barrier/iter)
    gemm_mma_h<1><<<GEMM_GRID, 128, GEMM_SMEM>>>(
        xh, wq, nullptr, qkvh, Mv, Dv, 3 * Dv);

    // 2) Causal flash attention (1-pass QK, 1-pass PV, 1 barrier/tile)
    {
        dim3 g(Sv / BQa, Hv, Bv);
        attn_mma<<<g, 256, ATTN_SMEM>>>(qkvh, oh);
    }

    // 3) Output projection (single-pass fp16) -> fp32 out
    gemm_mma_h<0><<<GEMM_GRID, 128, GEMM_SMEM>>>(
        oh, wo, out, nullptr, Mv, Dv, Dv);
}